// round 16
// baseline (speedup 1.0000x reference)
#include <cuda_runtime.h>
#include <cuda_bf16.h>
#include <cstdint>

#define N_NODES 100000
#define N_EDGES 1600000
#define D 128
#define H 8
#define DH 16
#define DFF 256
#define CAP 96

// ---------------- scratch (device globals; no allocation allowed) ----------
__device__ float g_Q[N_NODES * D];
__device__ float g_KV[(long)N_NODES * 2 * D];   // [node][K 0..127 | V 128..255]
__device__ float g_wV[N_NODES * D];
__device__ float g_z[N_NODES * H];
__device__ int   g_cnt[N_NODES];
__device__ int   g_csr[(long)N_NODES * CAP];

// bf16 hi/lo weight images (row-major [k][c], exactly the MMA B operand)
__device__ __nv_bfloat16 g_Bh[3 * 16384],  g_Bl[3 * 16384];   // Wq,Wk,Wv
__device__ __nv_bfloat16 g_Woh[16384],     g_Wol[16384];
__device__ __nv_bfloat16 g_W1h[32768],     g_W1l[32768];
__device__ __nv_bfloat16 g_W2h[32768],     g_W2l[32768];

// ---------------- mma.sync helpers ------------------------------------------
__device__ __forceinline__ uint32_t smem_u32(const void* p) {
    uint32_t a;
    asm("{ .reg .u64 t; cvta.to.shared.u64 t, %1; cvt.u32.u64 %0, t; }"
        : "=r"(a) : "l"(p));
    return a;
}
__device__ __forceinline__ void ldsm_x4(uint32_t* r, uint32_t addr) {
    asm volatile("ldmatrix.sync.aligned.m8n8.x4.shared.b16 {%0,%1,%2,%3}, [%4];"
                 : "=r"(r[0]), "=r"(r[1]), "=r"(r[2]), "=r"(r[3]) : "r"(addr));
}
__device__ __forceinline__ void ldsm_x4_t(uint32_t* r, uint32_t addr) {
    asm volatile("ldmatrix.sync.aligned.m8n8.x4.trans.shared.b16 {%0,%1,%2,%3}, [%4];"
                 : "=r"(r[0]), "=r"(r[1]), "=r"(r[2]), "=r"(r[3]) : "r"(addr));
}
__device__ __forceinline__ void mma_bf16(float* d, const uint32_t* a,
                                         uint32_t b0, uint32_t b1) {
    asm volatile(
        "mma.sync.aligned.m16n8k16.row.col.f32.bf16.bf16.f32 "
        "{%0,%1,%2,%3}, {%4,%5,%6,%7}, {%8,%9}, {%0,%1,%2,%3};"
        : "+f"(d[0]), "+f"(d[1]), "+f"(d[2]), "+f"(d[3])
        : "r"(a[0]), "r"(a[1]), "r"(a[2]), "r"(a[3]), "r"(b0), "r"(b1));
}
__device__ __forceinline__ uint32_t pack2(__nv_bfloat16 a, __nv_bfloat16 b) {
    __nv_bfloat162 t; t.x = a; t.y = b;
    return *reinterpret_cast<uint32_t*>(&t);
}
__device__ __forceinline__ void cvt_hilo4(float4 v, uint2& hu, uint2& lu) {
    __nv_bfloat16 hx = __float2bfloat16(v.x), hy = __float2bfloat16(v.y);
    __nv_bfloat16 hz = __float2bfloat16(v.z), hw = __float2bfloat16(v.w);
    hu.x = pack2(hx, hy); hu.y = pack2(hz, hw);
    lu.x = pack2(__float2bfloat16(v.x - __bfloat162float(hx)),
                 __float2bfloat16(v.y - __bfloat162float(hy)));
    lu.y = pack2(__float2bfloat16(v.z - __bfloat162float(hz)),
                 __float2bfloat16(v.w - __bfloat162float(hw)));
}
__device__ __forceinline__ void cvt_hilo2(float a, float b, uint32_t& hv, uint32_t& lv) {
    __nv_bfloat16 ha = __float2bfloat16(a), hb = __float2bfloat16(b);
    hv = pack2(ha, hb);
    lv = pack2(__float2bfloat16(a - __bfloat162float(ha)),
               __float2bfloat16(b - __bfloat162float(hb)));
}

// ---------------- weight prep + counter zero ---------------------------------
__global__ void bprep_kernel(
    const float* __restrict__ Wq, const float* __restrict__ Wk,
    const float* __restrict__ Wv, const float* __restrict__ Wo,
    const float* __restrict__ W1, const float* __restrict__ W2)
{
    int m = blockIdx.y;
    if (m == 6) {   // zero in-degree counters (grid-stride)
        for (int i = blockIdx.x * 256 + threadIdx.x; i < N_NODES; i += 128 * 256)
            g_cnt[i] = 0;
        return;
    }
    const float* W; __nv_bfloat16 *oh, *ol; int tot;
    switch (m) {
        case 0: W = Wq; oh = g_Bh;          ol = g_Bl;          tot = 16384; break;
        case 1: W = Wk; oh = g_Bh + 16384;  ol = g_Bl + 16384;  tot = 16384; break;
        case 2: W = Wv; oh = g_Bh + 32768;  ol = g_Bl + 32768;  tot = 16384; break;
        case 3: W = Wo; oh = g_Woh;         ol = g_Wol;         tot = 16384; break;
        case 4: W = W1; oh = g_W1h;         ol = g_W1l;         tot = 32768; break;
        default:W = W2; oh = g_W2h;         ol = g_W2l;         tot = 32768; break;
    }
    int idx = blockIdx.x * 256 + threadIdx.x;
    if (idx >= tot) return;
    float x = W[idx];
    __nv_bfloat16 hb = __float2bfloat16(x);
    oh[idx] = hb;
    ol[idx] = __float2bfloat16(x - __bfloat162float(hb));
}

// ---------------- generic B-chunk copy (128 rows x 128 cols, 272B stride) ----
__device__ __forceinline__ void copy_bchunk(
    char* dstH, char* dstL,
    const __nv_bfloat16* srcH, const __nv_bfloat16* srcL,
    int srcStride, int rowOff, int colOff, int tid)
{
    for (int ch = tid; ch < 2048; ch += 256) {
        int row = ch >> 4, o = ch & 15;
        long idx = (long)(rowOff + row) * srcStride + colOff + o * 8;
        *(uint4*)(dstH + row * 272 + o * 16) = *(const uint4*)(srcH + idx);
        *(uint4*)(dstL + row * 272 + o * 16) = *(const uint4*)(srcL + idx);
    }
}

// ---------------- 3-pass hi/lo GEMM: per warp m32 x n32 (R13 form) -----------
__device__ __forceinline__ void gemm3pass(
    uint32_t AhU, uint32_t AlU, int astride, int kOff,
    uint32_t BhU, uint32_t BlU,
    int mbase, int nbase, int lane, float acc[2][4][4])
{
#pragma unroll 1
    for (int pass = 0; pass < 3; pass++) {
        uint32_t Abase = (pass == 2) ? AlU : AhU;
        uint32_t Bbase = (pass == 1) ? BlU : BhU;
#pragma unroll 1
        for (int kt = 0; kt < 8; kt++) {
            uint32_t a[2][4];
#pragma unroll
            for (int mt = 0; mt < 2; mt++) {
                uint32_t addr = Abase
                    + (mbase + mt * 16 + (lane & 15)) * astride
                    + kOff + kt * 32 + (lane >> 4) * 16;
                ldsm_x4(a[mt], addr);
            }
            int g = lane >> 3, r8 = lane & 7;
#pragma unroll
            for (int nt2 = 0; nt2 < 2; nt2++) {
                uint32_t b[4];
                uint32_t baddr = Bbase
                    + (kt * 16 + (g & 1) * 8 + r8) * 272
                    + (nbase + nt2 * 16 + (g >> 1) * 8) * 2;
                ldsm_x4_t(b, baddr);
#pragma unroll
                for (int mt = 0; mt < 2; mt++) {
                    mma_bf16(acc[mt][nt2 * 2],     a[mt], b[0], b[1]);
                    mma_bf16(acc[mt][nt2 * 2 + 1], a[mt], b[2], b[3]);
                }
            }
        }
    }
}

// ---------------- QKV via mma.sync (128-node tile, R13 form) -----------------
#define ASTRIDE_B 272
#define PART_BYTES (128 * ASTRIDE_B)
#define QKV_SMEM (4 * PART_BYTES)

__global__ __launch_bounds__(256) void qkv_mma_kernel(const float* __restrict__ h)
{
    extern __shared__ char smem[];
    char* Ah = smem;
    char* Al = smem + PART_BYTES;
    char* Bh = smem + 2 * PART_BYTES;
    char* Bl = smem + 3 * PART_BYTES;

    int tid = threadIdx.x;
    int lane = tid & 31;
    int w = tid >> 5;
    int n0 = blockIdx.x * 128;

    {
        int r = tid >> 1;
        int half = tid & 1;
        int n = n0 + r;
        const float4* hp = (const float4*)(h + (long)n * D + half * 64);
        char* dh = Ah + r * ASTRIDE_B + half * 128;
        char* dl = Al + r * ASTRIDE_B + half * 128;
        bool ok = (n < N_NODES);
#pragma unroll
        for (int j = 0; j < 16; j++) {
            float4 v = ok ? hp[j] : make_float4(0.f, 0.f, 0.f, 0.f);
            uint2 hu, lu;
            cvt_hilo4(v, hu, lu);
            *(uint2*)(dh + j * 8) = hu;
            *(uint2*)(dl + j * 8) = lu;
        }
    }

    uint32_t AhU = smem_u32(Ah), AlU = smem_u32(Al);
    uint32_t BhU = smem_u32(Bh), BlU = smem_u32(Bl);

    int mbase = (w >> 2) * 64;
    int nbase = (w & 3) * 32;

#pragma unroll 1
    for (int m = 0; m < 3; m++) {
        __syncthreads();
        {
            const uint4* sh = (const uint4*)(g_Bh + m * 16384);
            const uint4* sl = (const uint4*)(g_Bl + m * 16384);
            for (int ch = tid; ch < 2048; ch += 256) {
                int row = ch >> 4, o = ch & 15;
                *(uint4*)(Bh + row * ASTRIDE_B + o * 16) = sh[ch];
                *(uint4*)(Bl + row * ASTRIDE_B + o * 16) = sl[ch];
            }
        }
        __syncthreads();

        float acc[4][4][4];
#pragma unroll
        for (int mt = 0; mt < 4; mt++)
#pragma unroll
            for (int nt = 0; nt < 4; nt++)
#pragma unroll
                for (int q = 0; q < 4; q++) acc[mt][nt][q] = 0.f;

#pragma unroll 1
        for (int pass = 0; pass < 3; pass++) {
            uint32_t Abase = (pass == 2) ? AlU : AhU;
            uint32_t Bbase = (pass == 1) ? BlU : BhU;
#pragma unroll 1
            for (int kt = 0; kt < 8; kt++) {
                uint32_t a[4][4];
#pragma unroll
                for (int mt = 0; mt < 4; mt++) {
                    uint32_t addr = Abase
                        + (mbase + mt * 16 + (lane & 15)) * ASTRIDE_B
                        + kt * 32 + (lane >> 4) * 16;
                    ldsm_x4(a[mt], addr);
                }
                int g = lane >> 3, r8 = lane & 7;
#pragma unroll
                for (int nt2 = 0; nt2 < 2; nt2++) {
                    uint32_t b[4];
                    uint32_t baddr = Bbase
                        + (kt * 16 + (g & 1) * 8 + r8) * ASTRIDE_B
                        + (nbase + nt2 * 16 + (g >> 1) * 8) * 2;
                    ldsm_x4_t(b, baddr);
#pragma unroll
                    for (int mt = 0; mt < 4; mt++) {
                        mma_bf16(acc[mt][nt2 * 2],     a[mt], b[0], b[1]);
                        mma_bf16(acc[mt][nt2 * 2 + 1], a[mt], b[2], b[3]);
                    }
                }
            }
        }

        float* base = (m == 0) ? g_Q : (m == 1) ? g_KV : g_KV + D;
        long stride = (m == 0) ? D : 2 * D;
        int gid = lane >> 2, q4 = lane & 3;
#pragma unroll
        for (int mt = 0; mt < 4; mt++)
#pragma unroll
            for (int nt = 0; nt < 4; nt++) {
                int row = n0 + mbase + mt * 16 + gid;
                int col = nbase + nt * 8 + q4 * 2;
                if (row < N_NODES)
                    *(float2*)&base[(long)row * stride + col] =
                        make_float2(acc[mt][nt][0], acc[mt][nt][1]);
                if (row + 8 < N_NODES)
                    *(float2*)&base[(long)(row + 8) * stride + col] =
                        make_float2(acc[mt][nt][2], acc[mt][nt][3]);
            }
    }
}

// ---------------- scatter -----------------------------------------------------
__global__ __launch_bounds__(256) void scatter_kernel(
    const int* __restrict__ src, const int* __restrict__ dst)
{
    int e = blockIdx.x * 256 + threadIdx.x;
    if (e >= N_EDGES) return;
    int d = dst[e];
    int pos = atomicAdd(&g_cnt[d], 1);
    if (pos < CAP) g_csr[(long)d * CAP + pos] = src[e];
}

// ---------------- aggregation: one warp per dst, 3-deep rolling pipeline ------
__global__ __launch_bounds__(256) void agg_kernel()
{
    int n = blockIdx.x * 8 + (threadIdx.x >> 5);
    int lane = threadIdx.x & 31;

    float4 q = *(const float4*)&g_Q[(long)n * D + lane * 4];
    float4 acc = make_float4(0.f, 0.f, 0.f, 0.f);
    float accz = 0.f;

    int deg = g_cnt[n];
    if (deg > CAP) deg = CAP;
    const int* __restrict__ lst = &g_csr[(long)n * CAP];

    float4 kf[3], vf[3];
#pragma unroll
    for (int u = 0; u < 3; u++) {
        if (u < deg) {
            int s = __ldg(&lst[u]);
            kf[u] = __ldg((const float4*)&g_KV[(long)s * 2 * D + lane * 4]);
            vf[u] = __ldg((const float4*)&g_KV[(long)s * 2 * D + D + lane * 4]);
        }
    }

    for (int j = 0; j < deg; j += 3) {
#pragma unroll
        for (int u = 0; u < 3; u++) {
            if (j + u < deg) {
                float4 kc = kf[u], vc = vf[u];
                if (j + u + 3 < deg) {
                    int s = __ldg(&lst[j + u + 3]);
                    kf[u] = __ldg((const float4*)&g_KV[(long)s * 2 * D + lane * 4]);
                    vf[u] = __ldg((const float4*)&g_KV[(long)s * 2 * D + D + lane * 4]);
                }
                float ps = kc.x * q.x + kc.y * q.y + kc.z * q.z + kc.w * q.w;
                ps += __shfl_xor_sync(0xffffffff, ps, 1);
                ps += __shfl_xor_sync(0xffffffff, ps, 2);
                float sc = __expf(fminf(fmaxf(ps * 0.25f, -5.f), 5.f));
                acc.x += sc * vc.x; acc.y += sc * vc.y;
                acc.z += sc * vc.z; acc.w += sc * vc.w;
                accz += sc;
            }
        }
    }

    *(float4*)&g_wV[(long)n * D + lane * 4] = acc;
    if ((lane & 3) == 0) g_z[(long)n * H + (lane >> 2)] = accz;
}

// ---------------- epilogue via mma.sync (R13 form) ---------------------------
#define EPI_X    0
#define EPI_AXH  33792
#define EPI_AXL  51200
#define EPI_AFH  68608
#define EPI_AFL  102400
#define EPI_BH   136192
#define EPI_BL   171008
#define EPI_SMEM 205824

__global__ __launch_bounds__(256) void epi_mma_kernel(
    const float* __restrict__ h,
    const float* __restrict__ bo,
    const float* __restrict__ ln1g, const float* __restrict__ ln1b,
    const float* __restrict__ b1,  const float* __restrict__ b2,
    const float* __restrict__ ln2g, const float* __restrict__ ln2b,
    float* __restrict__ out)
{
    extern __shared__ char smem[];
    float* X = (float*)(smem + EPI_X);

    int tid = threadIdx.x;
    int lane = tid & 31;
    int w = tid >> 5;
    int n0 = blockIdx.x * 64;

    uint32_t aXh = smem_u32(smem + EPI_AXH), aXl = smem_u32(smem + EPI_AXL);
    uint32_t aFh = smem_u32(smem + EPI_AFH), aFl = smem_u32(smem + EPI_AFL);
    uint32_t BhU = smem_u32(smem + EPI_BH),  BlU = smem_u32(smem + EPI_BL);

    int mbase = (w >> 2) * 32;
    int nbase = (w & 3) * 32;
    int gid = lane >> 2, q4 = lane & 3;

    // step 1: A = wV/(z+eps) -> actX hi/lo
    {
        int r = tid >> 2;
        int q = tid & 3;
        int n = n0 + r;
        bool ok = (n < N_NODES);
        float inv0 = ok ? 1.f / (g_z[(long)n * H + q * 2]     + 1e-6f) : 0.f;
        float inv1 = ok ? 1.f / (g_z[(long)n * H + q * 2 + 1] + 1e-6f) : 0.f;
        const float4* src = (const float4*)&g_wV[(long)n * D + q * 32];
#pragma unroll
        for (int j = 0; j < 8; j++) {
            float4 v = ok ? src[j] : make_float4(0.f, 0.f, 0.f, 0.f);
            float iv = (j < 4) ? inv0 : inv1;
            v.x *= iv; v.y *= iv; v.z *= iv; v.w *= iv;
            uint2 hu, lu;
            cvt_hilo4(v, hu, lu);
            *(uint2*)(smem + EPI_AXH + r * 272 + q * 64 + j * 8) = hu;
            *(uint2*)(smem + EPI_AXL + r * 272 + q * 64 + j * 8) = lu;
        }
    }
    __syncthreads();

    // GEMM1: X = h + A @ Wo + bo
    copy_bchunk(smem + EPI_BH, smem + EPI_BL, g_Woh, g_Wol, 128, 0, 0, tid);
    __syncthreads();
    {
        float acc[2][4][4];
#pragma unroll
        for (int mt = 0; mt < 2; mt++)
#pragma unroll
            for (int nt = 0; nt < 4; nt++)
#pragma unroll
                for (int q = 0; q < 4; q++) acc[mt][nt][q] = 0.f;
        gemm3pass(aXh, aXl, 272, 0, BhU, BlU, mbase, nbase, lane, acc);
#pragma unroll
        for (int mt = 0; mt < 2; mt++)
#pragma unroll
            for (int nt = 0; nt < 4; nt++) {
                int r = mbase + mt * 16 + gid;
                int col = nbase + nt * 8 + q4 * 2;
                float2 bov = *(const float2*)&bo[col];
                int n = n0 + r;
                float2 h0 = (n < N_NODES)
                    ? *(const float2*)&h[(long)n * D + col] : make_float2(0.f, 0.f);
                float2 h1 = (n + 8 < N_NODES)
                    ? *(const float2*)&h[(long)(n + 8) * D + col] : make_float2(0.f, 0.f);
                *(float2*)&X[r * 132 + col] =
                    make_float2(h0.x + acc[mt][nt][0] + bov.x,
                                h0.y + acc[mt][nt][1] + bov.y);
                *(float2*)&X[(r + 8) * 132 + col] =
                    make_float2(h1.x + acc[mt][nt][2] + bov.x,
                                h1.y + acc[mt][nt][3] + bov.y);
            }
    }
    __syncthreads();

    // LN1 + convert to actX hi/lo
    {
        float4 gv = *(const float4*)&ln1g[lane * 4];
        float4 bv = *(const float4*)&ln1b[lane * 4];
#pragma unroll
        for (int i = 0; i < 8; i++) {
            int r = w * 8 + i;
            float4 v = *(float4*)&X[r * 132 + lane * 4];
            float s  = v.x + v.y + v.z + v.w;
            float sq = v.x * v.x + v.y * v.y + v.z * v.z + v.w * v.w;
#pragma unroll
            for (int off = 16; off >= 1; off >>= 1) {
                s  += __shfl_xor_sync(0xffffffff, s, off);
                sq += __shfl_xor_sync(0xffffffff, sq, off);
            }
            float mu  = s * (1.f / D);
            float var = sq * (1.f / D) - mu * mu;
            float rs  = rsqrtf(var + 1e-5f);
            float4 o;
            o.x = (v.x - mu) * rs * gv.x + bv.x;
            o.y = (v.y - mu) * rs * gv.y + bv.y;
            o.z = (v.z - mu) * rs * gv.z + bv.z;
            o.w = (v.w - mu) * rs * gv.w + bv.w;
            *(float4*)&X[r * 132 + lane * 4] = o;
            uint2 hu, lu;
            cvt_hilo4(o, hu, lu);
            *(uint2*)(smem + EPI_AXH + r * 272 + lane * 8) = hu;
            *(uint2*)(smem + EPI_AXL + r * 272 + lane * 8) = lu;
        }
    }

    // GEMM2: F = relu(X @ W1 + b1), two halves
#pragma unroll 1
    for (int cc = 0; cc < DFF; cc += 128) {
        __syncthreads();
        copy_bchunk(smem + EPI_BH, smem + EPI_BL, g_W1h, g_W1l, DFF, 0, cc, tid);
        __syncthreads();
        float acc[2][4][4];
#pragma unroll
        for (int mt = 0; mt < 2; mt++)
#pragma unroll
            for (int nt = 0; nt < 4; nt++)
#pragma unroll
                for (int q = 0; q < 4; q++) acc[mt][nt][q] = 0.f;
        gemm3pass(aXh, aXl, 272, 0, BhU, BlU, mbase, nbase, lane, acc);
#pragma unroll
        for (int mt = 0; mt < 2; mt++)
#pragma unroll
            for (int nt = 0; nt < 4; nt++) {
                int r = mbase + mt * 16 + gid;
                int col = nbase + nt * 8 + q4 * 2;
                float2 b1v = *(const float2*)&b1[cc + col];
                float f0 = fmaxf(acc[mt][nt][0] + b1v.x, 0.f);
                float f1 = fmaxf(acc[mt][nt][1] + b1v.y, 0.f);
                float f2 = fmaxf(acc[mt][nt][2] + b1v.x, 0.f);
                float f3 = fmaxf(acc[mt][nt][3] + b1v.y, 0.f);
                uint32_t hv, lv;
                cvt_hilo2(f0, f1, hv, lv);
                *(uint32_t*)(smem + EPI_AFH + r * 528 + (cc + col) * 2) = hv;
                *(uint32_t*)(smem + EPI_AFL + r * 528 + (cc + col) * 2) = lv;
                cvt_hilo2(f2, f3, hv, lv);
                *(uint32_t*)(smem + EPI_AFH + (r + 8) * 528 + (cc + col) * 2) = hv;
                *(uint32_t*)(smem + EPI_AFL + (r + 8) * 528 + (cc + col) * 2) = lv;
            }
    }

    // GEMM3: Y = X + F @ W2 + b2
    {
        float acc[2][4][4];
#pragma unroll
        for (int mt = 0; mt < 2; mt++)
#pragma unroll
            for (int nt = 0; nt < 4; nt++)
#pragma unroll
                for (int q = 0; q < 4; q++) acc[mt][nt][q] = 0.f;
#pragma unroll 1
        for (int kc = 0; kc < DFF; kc += 128) {
            __syncthreads();
            copy_bchunk(smem + EPI_BH, smem + EPI_BL, g_W2h, g_W2l, D, kc, 0, tid);
            __syncthreads();
            gemm3pass(aFh, aFl, 528, kc * 2, BhU, BlU, mbase, nbase, lane, acc);
        }
#pragma unroll
        for (int mt = 0; mt < 2; mt++)
#pragma unroll
            for (int nt = 0; nt < 4; nt++) {
                int r = mbase + mt * 16 + gid;
                int col = nbase + nt * 8 + q4 * 2;
                float2 b2v = *(const float2*)&b2[col];
                float2 x0 = *(float2*)&X[r * 132 + col];
                float2 x1 = *(float2*)&X[(r + 8) * 132 + col];
                *(float2*)&X[r * 132 + col] =
                    make_float2(x0.x + acc[mt][nt][0] + b2v.x,
                                x0.y + acc[mt][nt][1] + b2v.y);
                *(float2*)&X[(r + 8) * 132 + col] =
                    make_float2(x1.x + acc[mt][nt][2] + b2v.x,
                                x1.y + acc[mt][nt][3] + b2v.y);
            }
    }
    __syncthreads();

    // LN2 -> out
    {
        float4 gv = *(const float4*)&ln2g[lane * 4];
        float4 bv = *(const float4*)&ln2b[lane * 4];
#pragma unroll
        for (int i = 0; i < 8; i++) {
            int r = w * 8 + i;
            int n = n0 + r;
            float4 v = *(float4*)&X[r * 132 + lane * 4];
            float s  = v.x + v.y + v.z + v.w;
            float sq = v.x * v.x + v.y * v.y + v.z * v.z + v.w * v.w;
#pragma unroll
            for (int off = 16; off >= 1; off >>= 1) {
                s  += __shfl_xor_sync(0xffffffff, s, off);
                sq += __shfl_xor_sync(0xffffffff, sq, off);
            }
            float mu  = s * (1.f / D);
            float var = sq * (1.f / D) - mu * mu;
            float rs  = rsqrtf(var + 1e-5f);
            float4 o;
            o.x = (v.x - mu) * rs * gv.x + bv.x;
            o.y = (v.y - mu) * rs * gv.y + bv.y;
            o.z = (v.z - mu) * rs * gv.z + bv.z;
            o.w = (v.w - mu) * rs * gv.w + bv.w;
            if (n < N_NODES)
                *(float4*)&out[(long)n * D + lane * 4] = o;
        }
    }
}

// ---------------- launch ------------------------------------------------------
extern "C" void kernel_launch(void* const* d_in, const int* in_sizes, int n_in,
                              void* d_out, int out_size)
{
    const float* h    = (const float*)d_in[0];
    const int*   src  = (const int*)  d_in[1];
    const int*   dst  = (const int*)  d_in[2];
    const float* Wq   = (const float*)d_in[3];
    const float* Wk   = (const float*)d_in[4];
    const float* Wv   = (const float*)d_in[5];
    const float* Wo   = (const float*)d_in[6];
    const float* bo   = (const float*)d_in[7];
    const float* ln1g = (const float*)d_in[8];
    const float* ln1b = (const float*)d_in[9];
    const float* W1   = (const float*)d_in[10];
    const float* b1   = (const float*)d_in[11];
    const float* W2   = (const float*)d_in[12];
    const float* b2   = (const float*)d_in[13];
    const float* ln2g = (const float*)d_in[14];
    const float* ln2b = (const float*)d_in[15];
    float* out = (float*)d_out;

    cudaFuncSetAttribute(qkv_mma_kernel,
                         cudaFuncAttributeMaxDynamicSharedMemorySize, QKV_SMEM);
    cudaFuncSetAttribute(epi_mma_kernel,
                         cudaFuncAttributeMaxDynamicSharedMemorySize, EPI_SMEM);

    dim3 bgrid(128, 7);   // y=6 zeroes g_cnt
    bprep_kernel<<<bgrid, 256>>>(Wq, Wk, Wv, Wo, W1, W2);
    scatter_kernel<<<N_EDGES / 256, 256>>>(src, dst);
    qkv_mma_kernel<<<(N_NODES + 127) / 128, 256, QKV_SMEM>>>(h);
    agg_kernel<<<N_NODES / 8, 256>>>();
    epi_mma_kernel<<<(N_NODES + 63) / 64, 256, EPI_SMEM>>>(
        h, bo, ln1g, ln1b, b1, b2, ln2g, ln2b, out);
}

// round 17
// speedup vs baseline: 1.0998x; 1.0998x over previous
#include <cuda_runtime.h>
#include <cuda_bf16.h>
#include <cstdint>

#define N_NODES 100000
#define N_EDGES 1600000
#define D 128
#define H 8
#define DH 16
#define DFF 256
#define CAP 96

// ---------------- scratch (device globals; no allocation allowed) ----------
__device__ float g_Q[N_NODES * D];
__device__ float g_KV[(long)N_NODES * 2 * D];   // [node][K 0..127 | V 128..255]
__device__ float g_wV[N_NODES * D];
__device__ float g_z[N_NODES * H];
__device__ int   g_cnt[N_NODES];
__device__ int   g_csr[(long)N_NODES * CAP];

// bf16 hi/lo weight images (row-major [k][c], exactly the MMA B operand)
__device__ __nv_bfloat16 g_Bh[3 * 16384],  g_Bl[3 * 16384];   // Wq,Wk,Wv
__device__ __nv_bfloat16 g_Woh[16384],     g_Wol[16384];
__device__ __nv_bfloat16 g_W1h[32768],     g_W1l[32768];
__device__ __nv_bfloat16 g_W2h[32768],     g_W2l[32768];

// ---------------- mma.sync helpers ------------------------------------------
__device__ __forceinline__ uint32_t smem_u32(const void* p) {
    uint32_t a;
    asm("{ .reg .u64 t; cvta.to.shared.u64 t, %1; cvt.u32.u64 %0, t; }"
        : "=r"(a) : "l"(p));
    return a;
}
__device__ __forceinline__ void ldsm_x4(uint32_t* r, uint32_t addr) {
    asm volatile("ldmatrix.sync.aligned.m8n8.x4.shared.b16 {%0,%1,%2,%3}, [%4];"
                 : "=r"(r[0]), "=r"(r[1]), "=r"(r[2]), "=r"(r[3]) : "r"(addr));
}
__device__ __forceinline__ void ldsm_x4_t(uint32_t* r, uint32_t addr) {
    asm volatile("ldmatrix.sync.aligned.m8n8.x4.trans.shared.b16 {%0,%1,%2,%3}, [%4];"
                 : "=r"(r[0]), "=r"(r[1]), "=r"(r[2]), "=r"(r[3]) : "r"(addr));
}
__device__ __forceinline__ void mma_bf16(float* d, const uint32_t* a,
                                         uint32_t b0, uint32_t b1) {
    asm volatile(
        "mma.sync.aligned.m16n8k16.row.col.f32.bf16.bf16.f32 "
        "{%0,%1,%2,%3}, {%4,%5,%6,%7}, {%8,%9}, {%0,%1,%2,%3};"
        : "+f"(d[0]), "+f"(d[1]), "+f"(d[2]), "+f"(d[3])
        : "r"(a[0]), "r"(a[1]), "r"(a[2]), "r"(a[3]), "r"(b0), "r"(b1));
}
__device__ __forceinline__ uint32_t pack2(__nv_bfloat16 a, __nv_bfloat16 b) {
    __nv_bfloat162 t; t.x = a; t.y = b;
    return *reinterpret_cast<uint32_t*>(&t);
}
__device__ __forceinline__ void cvt_hilo4(float4 v, uint2& hu, uint2& lu) {
    __nv_bfloat16 hx = __float2bfloat16(v.x), hy = __float2bfloat16(v.y);
    __nv_bfloat16 hz = __float2bfloat16(v.z), hw = __float2bfloat16(v.w);
    hu.x = pack2(hx, hy); hu.y = pack2(hz, hw);
    lu.x = pack2(__float2bfloat16(v.x - __bfloat162float(hx)),
                 __float2bfloat16(v.y - __bfloat162float(hy)));
    lu.y = pack2(__float2bfloat16(v.z - __bfloat162float(hz)),
                 __float2bfloat16(v.w - __bfloat162float(hw)));
}
__device__ __forceinline__ void cvt_hilo2(float a, float b, uint32_t& hv, uint32_t& lv) {
    __nv_bfloat16 ha = __float2bfloat16(a), hb = __float2bfloat16(b);
    hv = pack2(ha, hb);
    lv = pack2(__float2bfloat16(a - __bfloat162float(ha)),
               __float2bfloat16(b - __bfloat162float(hb)));
}

// ---------------- weight prep + counter zero ---------------------------------
__global__ void bprep_kernel(
    const float* __restrict__ Wq, const float* __restrict__ Wk,
    const float* __restrict__ Wv, const float* __restrict__ Wo,
    const float* __restrict__ W1, const float* __restrict__ W2)
{
    int m = blockIdx.y;
    if (m == 6) {   // zero in-degree counters (grid-stride)
        for (int i = blockIdx.x * 256 + threadIdx.x; i < N_NODES; i += 128 * 256)
            g_cnt[i] = 0;
        return;
    }
    const float* W; __nv_bfloat16 *oh, *ol; int tot;
    switch (m) {
        case 0: W = Wq; oh = g_Bh;          ol = g_Bl;          tot = 16384; break;
        case 1: W = Wk; oh = g_Bh + 16384;  ol = g_Bl + 16384;  tot = 16384; break;
        case 2: W = Wv; oh = g_Bh + 32768;  ol = g_Bl + 32768;  tot = 16384; break;
        case 3: W = Wo; oh = g_Woh;         ol = g_Wol;         tot = 16384; break;
        case 4: W = W1; oh = g_W1h;         ol = g_W1l;         tot = 32768; break;
        default:W = W2; oh = g_W2h;         ol = g_W2l;         tot = 32768; break;
    }
    int idx = blockIdx.x * 256 + threadIdx.x;
    if (idx >= tot) return;
    float x = W[idx];
    __nv_bfloat16 hb = __float2bfloat16(x);
    oh[idx] = hb;
    ol[idx] = __float2bfloat16(x - __bfloat162float(hb));
}

// ---------------- generic B-chunk copy (128 rows x 128 cols, 272B stride) ----
__device__ __forceinline__ void copy_bchunk(
    char* dstH, char* dstL,
    const __nv_bfloat16* srcH, const __nv_bfloat16* srcL,
    int srcStride, int rowOff, int colOff, int tid)
{
    for (int ch = tid; ch < 2048; ch += 256) {
        int row = ch >> 4, o = ch & 15;
        long idx = (long)(rowOff + row) * srcStride + colOff + o * 8;
        *(uint4*)(dstH + row * 272 + o * 16) = *(const uint4*)(srcH + idx);
        *(uint4*)(dstL + row * 272 + o * 16) = *(const uint4*)(srcL + idx);
    }
}

// ---------------- 3-pass hi/lo GEMM: per warp m32 x n32 (R13 form) -----------
__device__ __forceinline__ void gemm3pass(
    uint32_t AhU, uint32_t AlU, int astride, int kOff,
    uint32_t BhU, uint32_t BlU,
    int mbase, int nbase, int lane, float acc[2][4][4])
{
#pragma unroll 1
    for (int pass = 0; pass < 3; pass++) {
        uint32_t Abase = (pass == 2) ? AlU : AhU;
        uint32_t Bbase = (pass == 1) ? BlU : BhU;
#pragma unroll 1
        for (int kt = 0; kt < 8; kt++) {
            uint32_t a[2][4];
#pragma unroll
            for (int mt = 0; mt < 2; mt++) {
                uint32_t addr = Abase
                    + (mbase + mt * 16 + (lane & 15)) * astride
                    + kOff + kt * 32 + (lane >> 4) * 16;
                ldsm_x4(a[mt], addr);
            }
            int g = lane >> 3, r8 = lane & 7;
#pragma unroll
            for (int nt2 = 0; nt2 < 2; nt2++) {
                uint32_t b[4];
                uint32_t baddr = Bbase
                    + (kt * 16 + (g & 1) * 8 + r8) * 272
                    + (nbase + nt2 * 16 + (g >> 1) * 8) * 2;
                ldsm_x4_t(b, baddr);
#pragma unroll
                for (int mt = 0; mt < 2; mt++) {
                    mma_bf16(acc[mt][nt2 * 2],     a[mt], b[0], b[1]);
                    mma_bf16(acc[mt][nt2 * 2 + 1], a[mt], b[2], b[3]);
                }
            }
        }
    }
}

// ---------------- QKV via mma.sync (128-node tile, R13 form) -----------------
#define ASTRIDE_B 272
#define PART_BYTES (128 * ASTRIDE_B)
#define QKV_SMEM (4 * PART_BYTES)

__global__ __launch_bounds__(256) void qkv_mma_kernel(const float* __restrict__ h)
{
    extern __shared__ char smem[];
    char* Ah = smem;
    char* Al = smem + PART_BYTES;
    char* Bh = smem + 2 * PART_BYTES;
    char* Bl = smem + 3 * PART_BYTES;

    int tid = threadIdx.x;
    int lane = tid & 31;
    int w = tid >> 5;
    int n0 = blockIdx.x * 128;

    {
        int r = tid >> 1;
        int half = tid & 1;
        int n = n0 + r;
        const float4* hp = (const float4*)(h + (long)n * D + half * 64);
        char* dh = Ah + r * ASTRIDE_B + half * 128;
        char* dl = Al + r * ASTRIDE_B + half * 128;
        bool ok = (n < N_NODES);
#pragma unroll
        for (int j = 0; j < 16; j++) {
            float4 v = ok ? hp[j] : make_float4(0.f, 0.f, 0.f, 0.f);
            uint2 hu, lu;
            cvt_hilo4(v, hu, lu);
            *(uint2*)(dh + j * 8) = hu;
            *(uint2*)(dl + j * 8) = lu;
        }
    }

    uint32_t AhU = smem_u32(Ah), AlU = smem_u32(Al);
    uint32_t BhU = smem_u32(Bh), BlU = smem_u32(Bl);

    int mbase = (w >> 2) * 64;
    int nbase = (w & 3) * 32;

#pragma unroll 1
    for (int m = 0; m < 3; m++) {
        __syncthreads();
        {
            const uint4* sh = (const uint4*)(g_Bh + m * 16384);
            const uint4* sl = (const uint4*)(g_Bl + m * 16384);
            for (int ch = tid; ch < 2048; ch += 256) {
                int row = ch >> 4, o = ch & 15;
                *(uint4*)(Bh + row * ASTRIDE_B + o * 16) = sh[ch];
                *(uint4*)(Bl + row * ASTRIDE_B + o * 16) = sl[ch];
            }
        }
        __syncthreads();

        float acc[4][4][4];
#pragma unroll
        for (int mt = 0; mt < 4; mt++)
#pragma unroll
            for (int nt = 0; nt < 4; nt++)
#pragma unroll
                for (int q = 0; q < 4; q++) acc[mt][nt][q] = 0.f;

#pragma unroll 1
        for (int pass = 0; pass < 3; pass++) {
            uint32_t Abase = (pass == 2) ? AlU : AhU;
            uint32_t Bbase = (pass == 1) ? BlU : BhU;
#pragma unroll 1
            for (int kt = 0; kt < 8; kt++) {
                uint32_t a[4][4];
#pragma unroll
                for (int mt = 0; mt < 4; mt++) {
                    uint32_t addr = Abase
                        + (mbase + mt * 16 + (lane & 15)) * ASTRIDE_B
                        + kt * 32 + (lane >> 4) * 16;
                    ldsm_x4(a[mt], addr);
                }
                int g = lane >> 3, r8 = lane & 7;
#pragma unroll
                for (int nt2 = 0; nt2 < 2; nt2++) {
                    uint32_t b[4];
                    uint32_t baddr = Bbase
                        + (kt * 16 + (g & 1) * 8 + r8) * ASTRIDE_B
                        + (nbase + nt2 * 16 + (g >> 1) * 8) * 2;
                    ldsm_x4_t(b, baddr);
#pragma unroll
                    for (int mt = 0; mt < 4; mt++) {
                        mma_bf16(acc[mt][nt2 * 2],     a[mt], b[0], b[1]);
                        mma_bf16(acc[mt][nt2 * 2 + 1], a[mt], b[2], b[3]);
                    }
                }
            }
        }

        float* base = (m == 0) ? g_Q : (m == 1) ? g_KV : g_KV + D;
        long stride = (m == 0) ? D : 2 * D;
        int gid = lane >> 2, q4 = lane & 3;
#pragma unroll
        for (int mt = 0; mt < 4; mt++)
#pragma unroll
            for (int nt = 0; nt < 4; nt++) {
                int row = n0 + mbase + mt * 16 + gid;
                int col = nbase + nt * 8 + q4 * 2;
                if (row < N_NODES)
                    *(float2*)&base[(long)row * stride + col] =
                        make_float2(acc[mt][nt][0], acc[mt][nt][1]);
                if (row + 8 < N_NODES)
                    *(float2*)&base[(long)(row + 8) * stride + col] =
                        make_float2(acc[mt][nt][2], acc[mt][nt][3]);
            }
    }
}

// ---------------- scatter: int4-vectorized (4 edges/thread) -------------------
__global__ __launch_bounds__(256) void scatter_kernel(
    const int* __restrict__ src, const int* __restrict__ dst)
{
    int base = (blockIdx.x * 256 + threadIdx.x) * 4;
    if (base >= N_EDGES) return;
    int4 s4 = *(const int4*)(src + base);
    int4 d4 = *(const int4*)(dst + base);
    int pos;
    pos = atomicAdd(&g_cnt[d4.x], 1);
    if (pos < CAP) g_csr[(long)d4.x * CAP + pos] = s4.x;
    pos = atomicAdd(&g_cnt[d4.y], 1);
    if (pos < CAP) g_csr[(long)d4.y * CAP + pos] = s4.y;
    pos = atomicAdd(&g_cnt[d4.z], 1);
    if (pos < CAP) g_csr[(long)d4.z * CAP + pos] = s4.z;
    pos = atomicAdd(&g_cnt[d4.w], 1);
    if (pos < CAP) g_csr[(long)d4.w * CAP + pos] = s4.w;
}

// ---------------- aggregation: one warp per dst, 2-deep pipeline (R13) --------
__global__ __launch_bounds__(256) void agg_kernel()
{
    int n = blockIdx.x * 8 + (threadIdx.x >> 5);
    int lane = threadIdx.x & 31;

    float4 q = *(const float4*)&g_Q[(long)n * D + lane * 4];
    float4 acc = make_float4(0.f, 0.f, 0.f, 0.f);
    float accz = 0.f;

    int deg = g_cnt[n];
    if (deg > CAP) deg = CAP;
    const int* __restrict__ lst = &g_csr[(long)n * CAP];

    float4 kA, vA, kB, vB;
    if (deg > 0) {
        int s = __ldg(&lst[0]);
        kA = __ldg((const float4*)&g_KV[(long)s * 2 * D + lane * 4]);
        vA = __ldg((const float4*)&g_KV[(long)s * 2 * D + D + lane * 4]);
    }
    if (deg > 1) {
        int s = __ldg(&lst[1]);
        kB = __ldg((const float4*)&g_KV[(long)s * 2 * D + lane * 4]);
        vB = __ldg((const float4*)&g_KV[(long)s * 2 * D + D + lane * 4]);
    }

    for (int j = 0; j < deg; j += 2) {
        float4 k0 = kA, v0 = vA, k1 = kB, v1 = vB;
        if (j + 2 < deg) {
            int s = __ldg(&lst[j + 2]);
            kA = __ldg((const float4*)&g_KV[(long)s * 2 * D + lane * 4]);
            vA = __ldg((const float4*)&g_KV[(long)s * 2 * D + D + lane * 4]);
        }
        if (j + 3 < deg) {
            int s = __ldg(&lst[j + 3]);
            kB = __ldg((const float4*)&g_KV[(long)s * 2 * D + lane * 4]);
            vB = __ldg((const float4*)&g_KV[(long)s * 2 * D + D + lane * 4]);
        }
        {
            float ps = k0.x * q.x + k0.y * q.y + k0.z * q.z + k0.w * q.w;
            ps += __shfl_xor_sync(0xffffffff, ps, 1);
            ps += __shfl_xor_sync(0xffffffff, ps, 2);
            float sc = __expf(fminf(fmaxf(ps * 0.25f, -5.f), 5.f));
            acc.x += sc * v0.x; acc.y += sc * v0.y;
            acc.z += sc * v0.z; acc.w += sc * v0.w;
            accz += sc;
        }
        if (j + 1 < deg) {
            float ps = k1.x * q.x + k1.y * q.y + k1.z * q.z + k1.w * q.w;
            ps += __shfl_xor_sync(0xffffffff, ps, 1);
            ps += __shfl_xor_sync(0xffffffff, ps, 2);
            float sc = __expf(fminf(fmaxf(ps * 0.25f, -5.f), 5.f));
            acc.x += sc * v1.x; acc.y += sc * v1.y;
            acc.z += sc * v1.z; acc.w += sc * v1.w;
            accz += sc;
        }
    }

    *(float4*)&g_wV[(long)n * D + lane * 4] = acc;
    if ((lane & 3) == 0) g_z[(long)n * H + (lane >> 2)] = accz;
}

// ---------------- epilogue via mma.sync (R13 form) ---------------------------
#define EPI_X    0
#define EPI_AXH  33792
#define EPI_AXL  51200
#define EPI_AFH  68608
#define EPI_AFL  102400
#define EPI_BH   136192
#define EPI_BL   171008
#define EPI_SMEM 205824

__global__ __launch_bounds__(256) void epi_mma_kernel(
    const float* __restrict__ h,
    const float* __restrict__ bo,
    const float* __restrict__ ln1g, const float* __restrict__ ln1b,
    const float* __restrict__ b1,  const float* __restrict__ b2,
    const float* __restrict__ ln2g, const float* __restrict__ ln2b,
    float* __restrict__ out)
{
    extern __shared__ char smem[];
    float* X = (float*)(smem + EPI_X);

    int tid = threadIdx.x;
    int lane = tid & 31;
    int w = tid >> 5;
    int n0 = blockIdx.x * 64;

    uint32_t aXh = smem_u32(smem + EPI_AXH), aXl = smem_u32(smem + EPI_AXL);
    uint32_t aFh = smem_u32(smem + EPI_AFH), aFl = smem_u32(smem + EPI_AFL);
    uint32_t BhU = smem_u32(smem + EPI_BH),  BlU = smem_u32(smem + EPI_BL);

    int mbase = (w >> 2) * 32;
    int nbase = (w & 3) * 32;
    int gid = lane >> 2, q4 = lane & 3;

    // step 1: A = wV/(z+eps) -> actX hi/lo
    {
        int r = tid >> 2;
        int q = tid & 3;
        int n = n0 + r;
        bool ok = (n < N_NODES);
        float inv0 = ok ? 1.f / (g_z[(long)n * H + q * 2]     + 1e-6f) : 0.f;
        float inv1 = ok ? 1.f / (g_z[(long)n * H + q * 2 + 1] + 1e-6f) : 0.f;
        const float4* src = (const float4*)&g_wV[(long)n * D + q * 32];
#pragma unroll
        for (int j = 0; j < 8; j++) {
            float4 v = ok ? src[j] : make_float4(0.f, 0.f, 0.f, 0.f);
            float iv = (j < 4) ? inv0 : inv1;
            v.x *= iv; v.y *= iv; v.z *= iv; v.w *= iv;
            uint2 hu, lu;
            cvt_hilo4(v, hu, lu);
            *(uint2*)(smem + EPI_AXH + r * 272 + q * 64 + j * 8) = hu;
            *(uint2*)(smem + EPI_AXL + r * 272 + q * 64 + j * 8) = lu;
        }
    }
    __syncthreads();

    // GEMM1: X = h + A @ Wo + bo
    copy_bchunk(smem + EPI_BH, smem + EPI_BL, g_Woh, g_Wol, 128, 0, 0, tid);
    __syncthreads();
    {
        float acc[2][4][4];
#pragma unroll
        for (int mt = 0; mt < 2; mt++)
#pragma unroll
            for (int nt = 0; nt < 4; nt++)
#pragma unroll
                for (int q = 0; q < 4; q++) acc[mt][nt][q] = 0.f;
        gemm3pass(aXh, aXl, 272, 0, BhU, BlU, mbase, nbase, lane, acc);
#pragma unroll
        for (int mt = 0; mt < 2; mt++)
#pragma unroll
            for (int nt = 0; nt < 4; nt++) {
                int r = mbase + mt * 16 + gid;
                int col = nbase + nt * 8 + q4 * 2;
                float2 bov = *(const float2*)&bo[col];
                int n = n0 + r;
                float2 h0 = (n < N_NODES)
                    ? *(const float2*)&h[(long)n * D + col] : make_float2(0.f, 0.f);
                float2 h1 = (n + 8 < N_NODES)
                    ? *(const float2*)&h[(long)(n + 8) * D + col] : make_float2(0.f, 0.f);
                *(float2*)&X[r * 132 + col] =
                    make_float2(h0.x + acc[mt][nt][0] + bov.x,
                                h0.y + acc[mt][nt][1] + bov.y);
                *(float2*)&X[(r + 8) * 132 + col] =
                    make_float2(h1.x + acc[mt][nt][2] + bov.x,
                                h1.y + acc[mt][nt][3] + bov.y);
            }
    }
    __syncthreads();

    // LN1 + convert to actX hi/lo
    {
        float4 gv = *(const float4*)&ln1g[lane * 4];
        float4 bv = *(const float4*)&ln1b[lane * 4];
#pragma unroll
        for (int i = 0; i < 8; i++) {
            int r = w * 8 + i;
            float4 v = *(float4*)&X[r * 132 + lane * 4];
            float s  = v.x + v.y + v.z + v.w;
            float sq = v.x * v.x + v.y * v.y + v.z * v.z + v.w * v.w;
#pragma unroll
            for (int off = 16; off >= 1; off >>= 1) {
                s  += __shfl_xor_sync(0xffffffff, s, off);
                sq += __shfl_xor_sync(0xffffffff, sq, off);
            }
            float mu  = s * (1.f / D);
            float var = sq * (1.f / D) - mu * mu;
            float rs  = rsqrtf(var + 1e-5f);
            float4 o;
            o.x = (v.x - mu) * rs * gv.x + bv.x;
            o.y = (v.y - mu) * rs * gv.y + bv.y;
            o.z = (v.z - mu) * rs * gv.z + bv.z;
            o.w = (v.w - mu) * rs * gv.w + bv.w;
            *(float4*)&X[r * 132 + lane * 4] = o;
            uint2 hu, lu;
            cvt_hilo4(o, hu, lu);
            *(uint2*)(smem + EPI_AXH + r * 272 + lane * 8) = hu;
            *(uint2*)(smem + EPI_AXL + r * 272 + lane * 8) = lu;
        }
    }

    // GEMM2: F = relu(X @ W1 + b1), two halves
#pragma unroll 1
    for (int cc = 0; cc < DFF; cc += 128) {
        __syncthreads();
        copy_bchunk(smem + EPI_BH, smem + EPI_BL, g_W1h, g_W1l, DFF, 0, cc, tid);
        __syncthreads();
        float acc[2][4][4];
#pragma unroll
        for (int mt = 0; mt < 2; mt++)
#pragma unroll
            for (int nt = 0; nt < 4; nt++)
#pragma unroll
                for (int q = 0; q < 4; q++) acc[mt][nt][q] = 0.f;
        gemm3pass(aXh, aXl, 272, 0, BhU, BlU, mbase, nbase, lane, acc);
#pragma unroll
        for (int mt = 0; mt < 2; mt++)
#pragma unroll
            for (int nt = 0; nt < 4; nt++) {
                int r = mbase + mt * 16 + gid;
                int col = nbase + nt * 8 + q4 * 2;
                float2 b1v = *(const float2*)&b1[cc + col];
                float f0 = fmaxf(acc[mt][nt][0] + b1v.x, 0.f);
                float f1 = fmaxf(acc[mt][nt][1] + b1v.y, 0.f);
                float f2 = fmaxf(acc[mt][nt][2] + b1v.x, 0.f);
                float f3 = fmaxf(acc[mt][nt][3] + b1v.y, 0.f);
                uint32_t hv, lv;
                cvt_hilo2(f0, f1, hv, lv);
                *(uint32_t*)(smem + EPI_AFH + r * 528 + (cc + col) * 2) = hv;
                *(uint32_t*)(smem + EPI_AFL + r * 528 + (cc + col) * 2) = lv;
                cvt_hilo2(f2, f3, hv, lv);
                *(uint32_t*)(smem + EPI_AFH + (r + 8) * 528 + (cc + col) * 2) = hv;
                *(uint32_t*)(smem + EPI_AFL + (r + 8) * 528 + (cc + col) * 2) = lv;
            }
    }

    // GEMM3: Y = X + F @ W2 + b2
    {
        float acc[2][4][4];
#pragma unroll
        for (int mt = 0; mt < 2; mt++)
#pragma unroll
            for (int nt = 0; nt < 4; nt++)
#pragma unroll
                for (int q = 0; q < 4; q++) acc[mt][nt][q] = 0.f;
#pragma unroll 1
        for (int kc = 0; kc < DFF; kc += 128) {
            __syncthreads();
            copy_bchunk(smem + EPI_BH, smem + EPI_BL, g_W2h, g_W2l, D, kc, 0, tid);
            __syncthreads();
            gemm3pass(aFh, aFl, 528, kc * 2, BhU, BlU, mbase, nbase, lane, acc);
        }
#pragma unroll
        for (int mt = 0; mt < 2; mt++)
#pragma unroll
            for (int nt = 0; nt < 4; nt++) {
                int r = mbase + mt * 16 + gid;
                int col = nbase + nt * 8 + q4 * 2;
                float2 b2v = *(const float2*)&b2[col];
                float2 x0 = *(float2*)&X[r * 132 + col];
                float2 x1 = *(float2*)&X[(r + 8) * 132 + col];
                *(float2*)&X[r * 132 + col] =
                    make_float2(x0.x + acc[mt][nt][0] + b2v.x,
                                x0.y + acc[mt][nt][1] + b2v.y);
                *(float2*)&X[(r + 8) * 132 + col] =
                    make_float2(x1.x + acc[mt][nt][2] + b2v.x,
                                x1.y + acc[mt][nt][3] + b2v.y);
            }
    }
    __syncthreads();

    // LN2 -> out
    {
        float4 gv = *(const float4*)&ln2g[lane * 4];
        float4 bv = *(const float4*)&ln2b[lane * 4];
#pragma unroll
        for (int i = 0; i < 8; i++) {
            int r = w * 8 + i;
            int n = n0 + r;
            float4 v = *(float4*)&X[r * 132 + lane * 4];
            float s  = v.x + v.y + v.z + v.w;
            float sq = v.x * v.x + v.y * v.y + v.z * v.z + v.w * v.w;
#pragma unroll
            for (int off = 16; off >= 1; off >>= 1) {
                s  += __shfl_xor_sync(0xffffffff, s, off);
                sq += __shfl_xor_sync(0xffffffff, sq, off);
            }
            float mu  = s * (1.f / D);
            float var = sq * (1.f / D) - mu * mu;
            float rs  = rsqrtf(var + 1e-5f);
            float4 o;
            o.x = (v.x - mu) * rs * gv.x + bv.x;
            o.y = (v.y - mu) * rs * gv.y + bv.y;
            o.z = (v.z - mu) * rs * gv.z + bv.z;
            o.w = (v.w - mu) * rs * gv.w + bv.w;
            if (n < N_NODES)
                *(float4*)&out[(long)n * D + lane * 4] = o;
        }
    }
}

// ---------------- launch ------------------------------------------------------
extern "C" void kernel_launch(void* const* d_in, const int* in_sizes, int n_in,
                              void* d_out, int out_size)
{
    const float* h    = (const float*)d_in[0];
    const int*   src  = (const int*)  d_in[1];
    const int*   dst  = (const int*)  d_in[2];
    const float* Wq   = (const float*)d_in[3];
    const float* Wk   = (const float*)d_in[4];
    const float* Wv   = (const float*)d_in[5];
    const float* Wo   = (const float*)d_in[6];
    const float* bo   = (const float*)d_in[7];
    const float* ln1g = (const float*)d_in[8];
    const float* ln1b = (const float*)d_in[9];
    const float* W1   = (const float*)d_in[10];
    const float* b1   = (const float*)d_in[11];
    const float* W2   = (const float*)d_in[12];
    const float* b2   = (const float*)d_in[13];
    const float* ln2g = (const float*)d_in[14];
    const float* ln2b = (const float*)d_in[15];
    float* out = (float*)d_out;

    cudaFuncSetAttribute(qkv_mma_kernel,
                         cudaFuncAttributeMaxDynamicSharedMemorySize, QKV_SMEM);
    cudaFuncSetAttribute(epi_mma_kernel,
                         cudaFuncAttributeMaxDynamicSharedMemorySize, EPI_SMEM);

    dim3 bgrid(128, 7);   // y=6 zeroes g_cnt
    bprep_kernel<<<bgrid, 256>>>(Wq, Wk, Wv, Wo, W1, W2);
    scatter_kernel<<<(N_EDGES / 4 + 255) / 256, 256>>>(src, dst);
    qkv_mma_kernel<<<(N_NODES + 127) / 128, 256, QKV_SMEM>>>(h);
    agg_kernel<<<N_NODES / 8, 256>>>();
    epi_mma_kernel<<<(N_NODES + 63) / 64, 256, EPI_SMEM>>>(
        h, bo, ln1g, ln1b, b1, b2, ln2g, ln2b, out);
}